// round 15
// baseline (speedup 1.0000x reference)
#include <cuda_runtime.h>
#include <cuda_fp16.h>
#include <math.h>

#define NNODES 20000
#define NEDGES 320000
#define HD 128
#define FSTR 68                  // pair-column stride (words), conflict-free
#define TM 64                    // GEMM tile rows
#define ZOFF (TM * FSTR)         // words per hi/lo array (64-row tile)
#define SMEM_FUSED_BYTES (6 * ZOFF * 4)   // 104448 B -> 2 blocks/SM
#define NPB 1000                 // nodes per scan block
#define NSB 20                   // scan blocks

// ---------------- scratch (static device allocations) ----------------
__device__ int   g_is64;
__device__ volatile int g_sync1;
__device__ volatile int g_sync2;
__device__ __align__(16) float g_deg[NNODES];
__device__ __align__(16) int   g_cnt[NNODES];
__device__ volatile int g_bsum_v[NSB];
__device__ volatile int g_bflag[NSB];
__device__ __align__(16) int   g_rowptr[NNODES + 4];
__device__ __align__(16) int   g_cur[NNODES + 4];
__device__ __align__(16) float g_dis[NNODES];
__device__ __align__(16) int   g_ecol[NEDGES];    // CSR (by dst): src node
__device__ __align__(16) float g_enorm[NEDGES];   // CSR (by dst): edge norm
__device__ __align__(16) float g_ax[(size_t)NNODES * HD];   // prop(x)
__device__ __align__(16) float g_ah[(size_t)NNODES * HD];   // prop(h)
__device__ __align__(16) __half g_y16[(size_t)NNODES * 512]; // pre-prop gate features (fp16)
// pre-split bf16 weights: [stream 16][ks 8][nt 16][lane 32] = (hi0,hi1,lo0,lo1)
__device__ __align__(16) uint4 g_Bp[16 * 8 * 16 * 32];

// bf16 truncation split of a k-pair (x0=even k, x1=odd k) into packed bf16x2 regs.
__device__ __forceinline__ void bf16_split_pair(float x0, float x1,
                                                unsigned &hi, unsigned &lo) {
    unsigned b0 = __float_as_uint(x0), b1 = __float_as_uint(x1);
    hi = __byte_perm(b0, b1, 0x7632);              // {lo16=top16(x0), hi16=top16(x1)}
    float l0 = x0 - __uint_as_float(b0 & 0xFFFF0000u);
    float l1 = x1 - __uint_as_float(b1 & 0xFFFF0000u);
    asm("cvt.rn.bf16x2.f32 %0, %1, %2;" : "=r"(lo) : "f"(l1), "f"(l0));
}

// ---------------- merged init (deg/cnt/flags/sync + dtype detect) + weight prep ----------------
// blocks 0..255: wprep; blocks 256..334: init; block 256 also runs dtype detect.
__global__ void k_init_wprep(const int* __restrict__ ei32,
                             const float* __restrict__ Wx0, const float* __restrict__ Wh0,
                             const float* __restrict__ Wx1, const float* __restrict__ Wh1) {
    int b = blockIdx.x, t = threadIdx.x;
    if (b < 256) {
        int idx = b * 256 + t;            // 0..65535
        int s    = idx >> 12;             // stream
        int ks   = (idx >> 9) & 7;        // k-step (k0 = ks*16)
        int nt   = (idx >> 5) & 15;       // n-tile (n0 = nt*8)
        int lane = idx & 31;
        const float* W;
        if (s < 4)       W = Wx0 + s * 16384;
        else if (s < 8)  W = Wh0 + (s - 4) * 16384;
        else if (s < 12) W = Wx1 + (s - 8) * 16384;
        else             W = Wh1 + (s - 12) * 16384;
        int tig = lane & 3, grp = lane >> 2;
        int k0 = ks * 16, n = nt * 8 + grp;
        float w0 = W[(k0 + 2 * tig)     * 128 + n];
        float w1 = W[(k0 + 2 * tig + 1) * 128 + n];
        float w2 = W[(k0 + 2 * tig + 8) * 128 + n];
        float w3 = W[(k0 + 2 * tig + 9) * 128 + n];
        unsigned h0, l0, h1, l1;
        bf16_split_pair(w0, w1, h0, l0);
        bf16_split_pair(w2, w3, h1, l1);
        g_Bp[idx] = make_uint4(h0, h1, l0, l1);
    } else {
        int i = (b - 256) * 256 + t;
        if (i < NNODES) { g_deg[i] = 1.0f; g_cnt[i] = 0; }   // self-loop weight 1
        if (i < NSB) { g_bflag[i] = 0; }
        if (i == 0) { g_sync1 = 0; g_sync2 = 0; }
        if (b == 256) {
            __shared__ int nz;
            if (t == 0) nz = 0;
            __syncthreads();
            if (t < 128) {
                if (ei32[2 * t + 1] != 0) atomicAdd(&nz, 1);
            }
            __syncthreads();
            if (t == 0) g_is64 = (nz == 0) ? 1 : 0;
        }
    }
}

// ---------------- 4-edge decode ----------------
__device__ __forceinline__ void edge_decode4(const void* __restrict__ ei_raw, int e4,
                                             int* s, int* d) {
    if (g_is64) {
        const long long* ei = (const long long*)ei_raw;
        longlong2 s01 = *(const longlong2*)(ei + e4);
        longlong2 s23 = *(const longlong2*)(ei + e4 + 2);
        longlong2 d01 = *(const longlong2*)(ei + NEDGES + e4);
        longlong2 d23 = *(const longlong2*)(ei + NEDGES + e4 + 2);
        s[0] = (int)s01.x; s[1] = (int)s01.y; s[2] = (int)s23.x; s[3] = (int)s23.y;
        d[0] = (int)d01.x; d[1] = (int)d01.y; d[2] = (int)d23.x; d[3] = (int)d23.y;
    } else {
        const int* ei = (const int*)ei_raw;
        int4 sv = *(const int4*)(ei + e4);
        int4 dv = *(const int4*)(ei + NEDGES + e4);
        s[0] = sv.x; s[1] = sv.y; s[2] = sv.z; s[3] = sv.w;
        d[0] = dv.x; d[1] = dv.y; d[2] = dv.z; d[3] = dv.w;
    }
#pragma unroll
    for (int i = 0; i < 4; i++) {
        if ((unsigned)s[i] >= NNODES) s[i] = 0;
        if ((unsigned)d[i] >= NNODES) d[i] = 0;
    }
}

// ---------------- single-kernel edge pipeline: histogram -> scan -> scatter ----------------
// grid 313 x 256 (single wave, co-resident -> software grid barriers are safe).
__global__ void __launch_bounds__(256) k_edges(const void* __restrict__ ei_raw,
                                               const float* __restrict__ w) {
    int b = blockIdx.x, t = threadIdx.x;
    int lane = t & 31, wid = t >> 5;
    int e4 = (b * 256 + t) * 4;
    bool ev = (e4 < NEDGES);
    int s[4], d[4];
    float4 wv = make_float4(0.f, 0.f, 0.f, 0.f);

    // phase 1: decode + histogram
    if (ev) {
        edge_decode4(ei_raw, e4, s, d);
        wv = *(const float4*)(w + e4);
        atomicAdd(&g_deg[d[0]], wv.x); atomicAdd(&g_cnt[d[0]], 1);
        atomicAdd(&g_deg[d[1]], wv.y); atomicAdd(&g_cnt[d[1]], 1);
        atomicAdd(&g_deg[d[2]], wv.z); atomicAdd(&g_cnt[d[2]], 1);
        atomicAdd(&g_deg[d[3]], wv.w); atomicAdd(&g_cnt[d[3]], 1);
    }
    // grid barrier 1
    __syncthreads();
    if (t == 0) {
        __threadfence();
        atomicAdd((int*)&g_sync1, 1);
        while (g_sync1 < (int)gridDim.x) {}
    }
    __syncthreads();

    // phase 2a: scan (blocks < NSB), 256 threads x 4 nodes
    __shared__ int wsum[8];
    __shared__ int sbase;
    if (b < NSB) {
        int base = b * NPB;
        bool act = (t < NPB / 4);          // t < 250
        int4 q = make_int4(0, 0, 0, 0);
        int tsum = 0;
        if (act) {
            q = *(const int4*)(g_cnt + base + 4 * t);
            tsum = q.x + q.y + q.z + q.w;
        }
        int incl = tsum;
#pragma unroll
        for (int off = 1; off < 32; off <<= 1) {
            int n = __shfl_up_sync(0xFFFFFFFFu, incl, off);
            if (lane >= off) incl += n;
        }
        if (lane == 31) wsum[wid] = incl;
        __syncthreads();
        if (t < 8) {
            int wv2 = wsum[t], wi = wv2;
#pragma unroll
            for (int off = 1; off < 8; off <<= 1) {
                int n = __shfl_up_sync(0xFFu, wi, off);
                if (t >= off) wi += n;
            }
            wsum[t] = wi - wv2;            // exclusive warp base
            if (t == 7) {
                g_bsum_v[b] = wi;          // block total
                __threadfence();
                g_bflag[b] = 1;
            }
        }
        if (wid == 0) {                    // decoupled lookback
            int xx = 0;
            if (lane < b) {
                while (g_bflag[lane] == 0) {}
                xx = g_bsum_v[lane];
            }
            __syncwarp();
#pragma unroll
            for (int off = 16; off > 0; off >>= 1) xx += __shfl_down_sync(0xFFFFFFFFu, xx, off);
            if (lane == 0) sbase = xx;
        }
        __syncthreads();
        if (act) {
            int excl = sbase + wsum[wid] + incl - tsum;
            int4 rp = make_int4(excl, excl + q.x, excl + q.x + q.y, excl + q.x + q.y + q.z);
            *(int4*)(g_rowptr + base + 4 * t) = rp;
            *(int4*)(g_cur + base + 4 * t) = rp;
        }
        if (b == NSB - 1 && t == 0) g_rowptr[NNODES] = NEDGES;
    }
    // phase 2b: dis (all blocks, 64 nodes each; 313*64 >= 20000)
    if (t < 64) {
        int i = b * 64 + t;
        if (i < NNODES) {
            float dg = g_deg[i];
            g_dis[i] = dg > 0.f ? rsqrtf(fmaxf(dg, 1e-12f)) : 0.f;
        }
    }
    // grid barrier 2
    __syncthreads();
    if (t == 0) {
        __threadfence();
        atomicAdd((int*)&g_sync2, 1);
        while (g_sync2 < (int)gridDim.x) {}
    }
    __syncthreads();

    // phase 3: scatter (indices still in registers)
    if (ev) {
        float wa[4] = {wv.x, wv.y, wv.z, wv.w};
#pragma unroll
        for (int i = 0; i < 4; i++) {
            int pos = atomicAdd(&g_cur[d[i]], 1);
            g_ecol[pos] = s[i];
            g_enorm[pos] = g_dis[s[i]] * wa[i] * g_dis[d[i]];
        }
    }
}

// ---------------- fused gather SpMM for x and h (F=128), one warp per node ----------------
__global__ void k_gather_xh(const float* __restrict__ x, const float* __restrict__ h) {
    int warp = (blockIdx.x * blockDim.x + threadIdx.x) >> 5;
    int lane = threadIdx.x & 31;
    if (warp >= NNODES) return;
    int n = warp;
    float sd = g_dis[n];
    float s2 = sd * sd;
    float4 xv = *((const float4*)(x + (size_t)n * HD) + lane);
    float4 hv = *((const float4*)(h + (size_t)n * HD) + lane);
    float4 ax = make_float4(s2 * xv.x, s2 * xv.y, s2 * xv.z, s2 * xv.w);
    float4 ah = make_float4(s2 * hv.x, s2 * hv.y, s2 * hv.z, s2 * hv.w);
    int e0 = g_rowptr[n], e1 = g_rowptr[n + 1];
#pragma unroll 4
    for (int e = e0; e < e1; ++e) {
        int c = g_ecol[e];
        float nm = g_enorm[e];
        float4 cx = *((const float4*)(x + (size_t)c * HD) + lane);
        float4 ch = *((const float4*)(h + (size_t)c * HD) + lane);
        ax.x = fmaf(nm, cx.x, ax.x); ax.y = fmaf(nm, cx.y, ax.y);
        ax.z = fmaf(nm, cx.z, ax.z); ax.w = fmaf(nm, cx.w, ax.w);
        ah.x = fmaf(nm, ch.x, ah.x); ah.y = fmaf(nm, ch.y, ah.y);
        ah.z = fmaf(nm, ch.z, ah.z); ah.w = fmaf(nm, ch.w, ah.w);
    }
    ((float4*)(g_ax + (size_t)n * HD))[lane] = ax;
    ((float4*)(g_ah + (size_t)n * HD))[lane] = ah;
}

// ---------------- tensor-core GEMM building blocks (m16n8k16 bf16, 3-term split) ----------------
// 256 threads = 8 warps = 2m x 4n over a 64x128 tile; each warp: 32 rows (mt 2) x 32 cols (nt 4).
#define MMA_BF16(c, a, bb0, bb1) \
    asm("mma.sync.aligned.m16n8k16.row.col.f32.bf16.bf16.f32 " \
        "{%0,%1,%2,%3},{%4,%5,%6,%7},{%8,%9},{%0,%1,%2,%3};" \
        : "+f"(c[0]), "+f"(c[1]), "+f"(c[2]), "+f"(c[3]) \
        : "r"(a[0]), "r"(a[1]), "r"(a[2]), "r"(a[3]), "r"(bb0), "r"(bb1))

// volatile (no memory clobber): cannot be moved across __syncthreads() (itself volatile asm),
// which is the only ordering that matters (staging stores -> barrier -> LDSM). Ordinary
// loads (B fragments) remain free to schedule around it.
#define LDSM_X4(r, addr) \
    asm volatile("ldmatrix.sync.aligned.m8n8.x4.shared.b16 {%0,%1,%2,%3}, [%4];" \
        : "=r"(r[0]), "=r"(r[1]), "=r"(r[2]), "=r"(r[3]) : "r"(addr))

// stage a 64x128 fp32 tile from global, split into hi/lo bf16x2-pair smem arrays (256 thr)
__device__ __forceinline__ void stage_split(const float* __restrict__ A, int lda, int row0,
                                            unsigned* hi_arr, unsigned* lo_arr) {
    int tid = threadIdx.x;
    float4 v[8];
#pragma unroll
    for (int i = 0; i < 8; i++) {
        int f = i * 256 + tid;            // 0..2047
        int row = f >> 5;                 // 0..63
        int c4 = (f & 31) * 4;            // 0..124
        int grow = row0 + row;
        v[i] = (grow < NNODES) ? *(const float4*)(A + (size_t)grow * lda + c4)
                               : make_float4(0.f, 0.f, 0.f, 0.f);
    }
#pragma unroll
    for (int i = 0; i < 8; i++) {
        int f = i * 256 + tid;
        int row = f >> 5;
        int pc = (f & 31) * 2;            // pair column (even)
        unsigned h0, l0, h1, l1;
        bf16_split_pair(v[i].x, v[i].y, h0, l0);
        bf16_split_pair(v[i].z, v[i].w, h1, l1);
        hi_arr[row * FSTR + pc] = h0; hi_arr[row * FSTR + pc + 1] = h1;
        lo_arr[row * FSTR + pc] = l0; lo_arr[row * FSTR + pc + 1] = l1;
    }
}

// acc += (smem A tile) @ (pre-split B stream), 3-term split; A frags via ldmatrix.
// B fragments register-double-buffered one k-step ahead to hide L2 latency.
__device__ __forceinline__ void mma_pass(float (*acc)[4][4],
                                         const unsigned* As_hi, const unsigned* As_lo,
                                         int stream) {
    int tid = threadIdx.x;
    int wid = tid >> 5, lane = tid & 31;
    int wm = wid >> 2, wn = wid & 3;
    int m0 = wm * 32;
    const uint4* __restrict__ Bpw = g_Bp + (stream << 12) + (wn * 4) * 32 + lane;
    int lrow = (lane & 7) + ((lane >> 3) & 1) * 8;
    int lcol = (lane >> 4) * 4;
    unsigned hi_base = (unsigned)__cvta_generic_to_shared(As_hi)
                     + ((m0 + lrow) * FSTR + lcol) * 4;
    unsigned lo_base = (unsigned)__cvta_generic_to_shared(As_lo)
                     + ((m0 + lrow) * FSTR + lcol) * 4;
    uint4 b[4], bn[4];
#pragma unroll
    for (int nt = 0; nt < 4; nt++) b[nt] = Bpw[nt * 32];
#pragma unroll
    for (int ks = 0; ks < 8; ks++) {
        if (ks < 7) {
#pragma unroll
            for (int nt = 0; nt < 4; nt++) bn[nt] = Bpw[((ks + 1) * 16 + nt) * 32];
        }
        unsigned ahi[2][4], alo[2][4];
#pragma unroll
        for (int mt = 0; mt < 2; mt++) {
            unsigned off = (mt * 16 * FSTR + ks * 8) * 4;
            LDSM_X4(ahi[mt], hi_base + off);
            LDSM_X4(alo[mt], lo_base + off);
        }
#pragma unroll
        for (int nt = 0; nt < 4; nt++) {
#pragma unroll
            for (int mt = 0; mt < 2; mt++) {
                float* c = acc[mt][nt];
                MMA_BF16(c, ahi[mt], b[nt].x, b[nt].y);   // hi*hi
                MMA_BF16(c, ahi[mt], b[nt].z, b[nt].w);   // hi*lo
                MMA_BF16(c, alo[mt], b[nt].x, b[nt].y);   // lo*hi
            }
        }
#pragma unroll
        for (int nt = 0; nt < 4; nt++) b[nt] = bn[nt];
    }
}

// relu(acc + bias) -> split -> z smem buffers (C-frag pair (c0,c1) is an adjacent k-pair)
__device__ __forceinline__ void store_z(float (*acc)[4][4], const float* __restrict__ bias,
                                        unsigned* zhi, unsigned* zlo) {
    int tid = threadIdx.x;
    int wid = tid >> 5, lane = tid & 31;
    int wm = wid >> 2, wn = wid & 3;
    int m0 = wm * 32, n0 = wn * 32;
    int tig = lane & 3, grp = lane >> 2;
#pragma unroll
    for (int nt = 0; nt < 4; nt++) {
        int col = n0 + nt * 8 + 2 * tig;
        float b0 = bias[col], b1 = bias[col + 1];
        int pc = col >> 1;
#pragma unroll
        for (int mt = 0; mt < 2; mt++) {
            int r = m0 + mt * 16 + grp;
            float* c = acc[mt][nt];
            float u0 = fmaxf(c[0] + b0, 0.f), u1 = fmaxf(c[1] + b1, 0.f);
            float u2 = fmaxf(c[2] + b0, 0.f), u3 = fmaxf(c[3] + b1, 0.f);
            unsigned h, l;
            bf16_split_pair(u0, u1, h, l);
            zhi[r * FSTR + pc] = h; zlo[r * FSTR + pc] = l;
            bf16_split_pair(u2, u3, h, l);
            zhi[(r + 8) * FSTR + pc] = h; zlo[(r + 8) * FSTR + pc] = l;
        }
    }
}

// write y as fp16 (halves gather traffic downstream)
__device__ __forceinline__ void gemm_epilogue_y16(float (*acc)[4][4],
                                                  __half* __restrict__ C, int ldc, int row0) {
    int tid = threadIdx.x;
    int wid = tid >> 5, lane = tid & 31;
    int wm = wid >> 2, wn = wid & 3;
    int m0 = wm * 32, n0 = wn * 32;
    int tig = lane & 3, grp = lane >> 2;
#pragma unroll
    for (int nt = 0; nt < 4; nt++) {
        int col = n0 + nt * 8 + 2 * tig;
#pragma unroll
        for (int mt = 0; mt < 2; mt++) {
            int r = row0 + m0 + mt * 16 + grp;
            float* c = acc[mt][nt];
            if (r < NNODES)
                *(__half2*)(C + (size_t)r * ldc + col) = __floats2half2_rn(c[0], c[1]);
            int r2 = r + 8;
            if (r2 < NNODES)
                *(__half2*)(C + (size_t)r2 * ldc + col) = __floats2half2_rn(c[2], c[3]);
        }
    }
}

// fused 2-layer GEMM per (gate, 64-row tile): z never leaves the SM. 256 threads, 2 blocks/SM.
__global__ __launch_bounds__(256) void k_mma_fused(const float* __restrict__ bx0,
                                                   const float* __restrict__ bh0) {
    extern __shared__ unsigned sm[];
    unsigned *Ah  = sm,            *Al  = sm + ZOFF;
    unsigned *zxh = sm + 2 * ZOFF, *zxl = sm + 3 * ZOFF;
    unsigned *zhh = sm + 4 * ZOFF, *zhl = sm + 5 * ZOFF;
    int g = blockIdx.y;
    int row0 = blockIdx.x * TM;

    // stage x -> (Ah,Al) and h -> (zhh,zhl) [h staging overlaps x MMA below]
    stage_split(g_ax, 128, row0, Ah, Al);
    stage_split(g_ah, 128, row0, zhh, zhl);
    __syncthreads();

    // layer-1 x-branch
    float accz[2][4][4];
#pragma unroll
    for (int a = 0; a < 2; a++)
#pragma unroll
        for (int b = 0; b < 4; b++)
#pragma unroll
            for (int cc = 0; cc < 4; cc++) accz[a][b][cc] = 0.f;
    mma_pass(accz, Ah, Al, g);
    store_z(accz, bx0 + g * 128, zxh, zxl);

    // layer-1 h-branch (A-h staged in zhh/zhl)
    float acch[2][4][4];
#pragma unroll
    for (int a = 0; a < 2; a++)
#pragma unroll
        for (int b = 0; b < 4; b++)
#pragma unroll
            for (int cc = 0; cc < 4; cc++) acch[a][b][cc] = 0.f;
    mma_pass(acch, zhh, zhl, 4 + g);
    __syncthreads();    // all warps finished reading A-h (and zxh writes now visible)
    store_z(acch, bh0 + g * 128, zhh, zhl);   // overwrite A-h with z_h
    __syncthreads();    // z_h visible

    // layer-2: y = z_x @ Wx1[g] + z_h @ Wh1[g]   (bias deferred to LSTM)
    float accy[2][4][4];
#pragma unroll
    for (int a = 0; a < 2; a++)
#pragma unroll
        for (int b = 0; b < 4; b++)
#pragma unroll
            for (int cc = 0; cc < 4; cc++) accy[a][b][cc] = 0.f;
    mma_pass(accy, zxh, zxl, 8 + g);
    mma_pass(accy, zhh, zhl, 12 + g);
    gemm_epilogue_y16(accy, g_y16 + g * 128, 512, row0);
}

// ---------------- fused F=512 gather (fp16 y) + LSTM epilogue: one block / node ----------------
__device__ __forceinline__ float sigmoidf_(float v) { return 1.f / (1.f + expf(-v)); }

__global__ void __launch_bounds__(128) k_gather_lstm(
    const float* __restrict__ c,
    const float* __restrict__ bx1, const float* __restrict__ bh1,
    const float* __restrict__ wc, const float* __restrict__ bg,
    float* __restrict__ out)
{
    __shared__ float sG[512];
    int n = blockIdx.x;
    int t = threadIdx.x;
    float sd = g_dis[n];
    float s2 = sd * sd;
    // thread t handles features 4t..4t+3 (8 bytes of fp16)
    uint2 raw = *(const uint2*)(g_y16 + (size_t)n * 512 + t * 4);
    float2 f0 = __half22float2(*(__half2*)&raw.x);
    float2 f1 = __half22float2(*(__half2*)&raw.y);
    float4 acc = make_float4(s2 * f0.x, s2 * f0.y, s2 * f1.x, s2 * f1.y);
    int e0 = g_rowptr[n], e1 = g_rowptr[n + 1];
#pragma unroll 4
    for (int e = e0; e < e1; ++e) {
        int cc = g_ecol[e];
        float nm = g_enorm[e];
        uint2 yr = *(const uint2*)(g_y16 + (size_t)cc * 512 + t * 4);
        float2 y0 = __half22float2(*(__half2*)&yr.x);
        float2 y1 = __half22float2(*(__half2*)&yr.y);
        acc.x = fmaf(nm, y0.x, acc.x); acc.y = fmaf(nm, y0.y, acc.y);
        acc.z = fmaf(nm, y1.x, acc.z); acc.w = fmaf(nm, y1.y, acc.w);
    }
    ((float4*)sG)[t] = acc;
    __syncthreads();
    int f = t;
    int idx = n * HD + f;
    float cv = c[idx];
    float Gi = sG[f]       + bx1[f]       + bh1[f];
    float Gf = sG[128 + f] + bx1[128 + f] + bh1[128 + f];
    float Gc = sG[256 + f] + bx1[256 + f] + bh1[256 + f];
    float Go = sG[384 + f] + bx1[384 + f] + bh1[384 + f];
    float I  = sigmoidf_(Gi + wc[f] * cv + bg[f]);
    float Fg = sigmoidf_(Gf + wc[128 + f] * cv + bg[128 + f]);
    float T  = tanhf(Gc + bg[256 + f]);
    float Cn = Fg * cv + I * T;
    float O  = sigmoidf_(Go + wc[256 + f] * Cn + bg[384 + f]);
    float Hn = O * tanhf(Cn);
    out[idx] = Hn;
    out[(size_t)NNODES * HD + idx] = Cn;
}

// ---------------- launch ----------------
extern "C" void kernel_launch(void* const* d_in, const int* in_sizes, int n_in,
                              void* d_out, int out_size) {
    const float* x   = (const float*)d_in[0];
    const void*  ei  = d_in[1];                 // int32 or int64, detected on device
    const float* w   = (const float*)d_in[2];
    const float* h   = (const float*)d_in[3];
    const float* c   = (const float*)d_in[4];
    const float* Wx0 = (const float*)d_in[5];
    const float* bx0 = (const float*)d_in[6];
    const float* Wx1 = (const float*)d_in[7];
    const float* bx1 = (const float*)d_in[8];
    const float* Wh0 = (const float*)d_in[9];
    const float* bh0 = (const float*)d_in[10];
    const float* Wh1 = (const float*)d_in[11];
    const float* bh1 = (const float*)d_in[12];
    const float* wc  = (const float*)d_in[13];
    const float* bg  = (const float*)d_in[14];
    float* out = (float*)d_out;

    static int smem_set = 0;
    if (!smem_set) {
        cudaFuncSetAttribute(k_mma_fused, cudaFuncAttributeMaxDynamicSharedMemorySize,
                             SMEM_FUSED_BYTES);
        smem_set = 1;
    }

    const int T = 256;
    // prologue: merged init+wprep, then single-kernel edge pipeline
    k_init_wprep<<<256 + (NNODES + T - 1) / T, T>>>((const int*)ei, Wx0, Wh0, Wx1, Wh1);
    k_edges<<<(NEDGES / 4 + T - 1) / T, T>>>(ei, w);

    // fused first props (F=128) for x and h, gather-based
    k_gather_xh<<<(NNODES * 32 + T - 1) / T, T>>>(x, h);

    // fused 2-layer tensor-core GEMM (z stays on-chip, y written fp16), 64-row tiles
    dim3 gm((NNODES + TM - 1) / TM, 4);
    k_mma_fused<<<gm, 256, SMEM_FUSED_BYTES>>>(bx0, bh0);

    // fused F=512 gather (fp16) + LSTM epilogue
    k_gather_lstm<<<NNODES, 128>>>(c, bx1, bh1, wc, bg, out);
}

// round 16
// speedup vs baseline: 1.0794x; 1.0794x over previous
#include <cuda_runtime.h>
#include <cuda_fp16.h>
#include <math.h>

#define NNODES 20000
#define NEDGES 320000
#define HD 128
#define FSTR 68                  // pair-column stride (words), conflict-free
#define TM 64                    // GEMM tile rows
#define ZOFF (TM * FSTR)         // words per hi/lo array (64-row tile)
#define SMEM_FUSED_BYTES (6 * ZOFF * 4)   // 104448 B -> 2 blocks/SM
#define NPB 1000                 // nodes per scan block
#define NSB 20                   // scan blocks

// ---------------- scratch (static device allocations) ----------------
__device__ int   g_is64;
__device__ volatile int g_sync1;
__device__ volatile int g_sync2;
__device__ __align__(16) float g_deg[NNODES];
__device__ __align__(16) int   g_cnt[NNODES];
__device__ volatile int g_bsum_v[NSB];
__device__ volatile int g_bflag[NSB];
__device__ __align__(16) int   g_rowptr[NNODES + 4];
__device__ __align__(16) int   g_cur[NNODES + 4];
__device__ __align__(16) float g_dis[NNODES];
__device__ __align__(16) int   g_ecol[NEDGES];    // CSR (by dst): src node
__device__ __align__(16) float g_enorm[NEDGES];   // CSR (by dst): edge norm
__device__ __align__(16) float g_ax[(size_t)NNODES * HD];   // prop(x)
__device__ __align__(16) float g_ah[(size_t)NNODES * HD];   // prop(h)
__device__ __align__(16) __half g_y16[(size_t)NNODES * 512]; // pre-prop gate features (fp16)
// pre-split bf16 weights: [stream 16][ks 8][nt 16][lane 32] = (hi0,hi1,lo0,lo1)
__device__ __align__(16) uint4 g_Bp[16 * 8 * 16 * 32];

// bf16 truncation split of a k-pair (x0=even k, x1=odd k) into packed bf16x2 regs.
__device__ __forceinline__ void bf16_split_pair(float x0, float x1,
                                                unsigned &hi, unsigned &lo) {
    unsigned b0 = __float_as_uint(x0), b1 = __float_as_uint(x1);
    hi = __byte_perm(b0, b1, 0x7632);              // {lo16=top16(x0), hi16=top16(x1)}
    float l0 = x0 - __uint_as_float(b0 & 0xFFFF0000u);
    float l1 = x1 - __uint_as_float(b1 & 0xFFFF0000u);
    asm("cvt.rn.bf16x2.f32 %0, %1, %2;" : "=r"(lo) : "f"(l1), "f"(l0));
}

// ---------------- merged init (deg/cnt/flags/sync + dtype detect) + weight prep ----------------
// blocks 0..255: wprep; blocks 256..334: init; block 256 also runs dtype detect.
__global__ void k_init_wprep(const int* __restrict__ ei32,
                             const float* __restrict__ Wx0, const float* __restrict__ Wh0,
                             const float* __restrict__ Wx1, const float* __restrict__ Wh1) {
    int b = blockIdx.x, t = threadIdx.x;
    if (b < 256) {
        int idx = b * 256 + t;            // 0..65535
        int s    = idx >> 12;             // stream
        int ks   = (idx >> 9) & 7;        // k-step (k0 = ks*16)
        int nt   = (idx >> 5) & 15;       // n-tile (n0 = nt*8)
        int lane = idx & 31;
        const float* W;
        if (s < 4)       W = Wx0 + s * 16384;
        else if (s < 8)  W = Wh0 + (s - 4) * 16384;
        else if (s < 12) W = Wx1 + (s - 8) * 16384;
        else             W = Wh1 + (s - 12) * 16384;
        int tig = lane & 3, grp = lane >> 2;
        int k0 = ks * 16, n = nt * 8 + grp;
        float w0 = W[(k0 + 2 * tig)     * 128 + n];
        float w1 = W[(k0 + 2 * tig + 1) * 128 + n];
        float w2 = W[(k0 + 2 * tig + 8) * 128 + n];
        float w3 = W[(k0 + 2 * tig + 9) * 128 + n];
        unsigned h0, l0, h1, l1;
        bf16_split_pair(w0, w1, h0, l0);
        bf16_split_pair(w2, w3, h1, l1);
        g_Bp[idx] = make_uint4(h0, h1, l0, l1);
    } else {
        int i = (b - 256) * 256 + t;
        if (i < NNODES) { g_deg[i] = 1.0f; g_cnt[i] = 0; }   // self-loop weight 1
        if (i < NSB) { g_bflag[i] = 0; }
        if (i == 0) { g_sync1 = 0; g_sync2 = 0; }
        if (b == 256) {
            __shared__ int nz;
            if (t == 0) nz = 0;
            __syncthreads();
            if (t < 128) {
                if (ei32[2 * t + 1] != 0) atomicAdd(&nz, 1);
            }
            __syncthreads();
            if (t == 0) g_is64 = (nz == 0) ? 1 : 0;
        }
    }
}

// ---------------- 4-edge decode ----------------
__device__ __forceinline__ void edge_decode4(const void* __restrict__ ei_raw, int e4,
                                             int* s, int* d) {
    if (g_is64) {
        const long long* ei = (const long long*)ei_raw;
        longlong2 s01 = *(const longlong2*)(ei + e4);
        longlong2 s23 = *(const longlong2*)(ei + e4 + 2);
        longlong2 d01 = *(const longlong2*)(ei + NEDGES + e4);
        longlong2 d23 = *(const longlong2*)(ei + NEDGES + e4 + 2);
        s[0] = (int)s01.x; s[1] = (int)s01.y; s[2] = (int)s23.x; s[3] = (int)s23.y;
        d[0] = (int)d01.x; d[1] = (int)d01.y; d[2] = (int)d23.x; d[3] = (int)d23.y;
    } else {
        const int* ei = (const int*)ei_raw;
        int4 sv = *(const int4*)(ei + e4);
        int4 dv = *(const int4*)(ei + NEDGES + e4);
        s[0] = sv.x; s[1] = sv.y; s[2] = sv.z; s[3] = sv.w;
        d[0] = dv.x; d[1] = dv.y; d[2] = dv.z; d[3] = dv.w;
    }
#pragma unroll
    for (int i = 0; i < 4; i++) {
        if ((unsigned)s[i] >= NNODES) s[i] = 0;
        if ((unsigned)d[i] >= NNODES) d[i] = 0;
    }
}

// ---------------- single-kernel edge pipeline: histogram -> scan -> scatter ----------------
// grid 313 x 256 (single wave, co-resident -> software grid barriers are safe).
__global__ void __launch_bounds__(256) k_edges(const void* __restrict__ ei_raw,
                                               const float* __restrict__ w) {
    int b = blockIdx.x, t = threadIdx.x;
    int lane = t & 31, wid = t >> 5;
    int e4 = (b * 256 + t) * 4;
    bool ev = (e4 < NEDGES);
    int s[4], d[4];
    float4 wv = make_float4(0.f, 0.f, 0.f, 0.f);

    // phase 1: decode + histogram
    if (ev) {
        edge_decode4(ei_raw, e4, s, d);
        wv = *(const float4*)(w + e4);
        atomicAdd(&g_deg[d[0]], wv.x); atomicAdd(&g_cnt[d[0]], 1);
        atomicAdd(&g_deg[d[1]], wv.y); atomicAdd(&g_cnt[d[1]], 1);
        atomicAdd(&g_deg[d[2]], wv.z); atomicAdd(&g_cnt[d[2]], 1);
        atomicAdd(&g_deg[d[3]], wv.w); atomicAdd(&g_cnt[d[3]], 1);
    }
    // grid barrier 1
    __syncthreads();
    if (t == 0) {
        __threadfence();
        atomicAdd((int*)&g_sync1, 1);
        while (g_sync1 < (int)gridDim.x) {}
    }
    __syncthreads();

    // phase 2a: scan (blocks < NSB), 256 threads x 4 nodes
    __shared__ int wsum[8];
    __shared__ int sbase;
    if (b < NSB) {
        int base = b * NPB;
        bool act = (t < NPB / 4);          // t < 250
        int4 q = make_int4(0, 0, 0, 0);
        int tsum = 0;
        if (act) {
            q = *(const int4*)(g_cnt + base + 4 * t);
            tsum = q.x + q.y + q.z + q.w;
        }
        int incl = tsum;
#pragma unroll
        for (int off = 1; off < 32; off <<= 1) {
            int n = __shfl_up_sync(0xFFFFFFFFu, incl, off);
            if (lane >= off) incl += n;
        }
        if (lane == 31) wsum[wid] = incl;
        __syncthreads();
        if (t < 8) {
            int wv2 = wsum[t], wi = wv2;
#pragma unroll
            for (int off = 1; off < 8; off <<= 1) {
                int n = __shfl_up_sync(0xFFu, wi, off);
                if (t >= off) wi += n;
            }
            wsum[t] = wi - wv2;            // exclusive warp base
            if (t == 7) {
                g_bsum_v[b] = wi;          // block total
                __threadfence();
                g_bflag[b] = 1;
            }
        }
        if (wid == 0) {                    // decoupled lookback
            int xx = 0;
            if (lane < b) {
                while (g_bflag[lane] == 0) {}
                xx = g_bsum_v[lane];
            }
            __syncwarp();
#pragma unroll
            for (int off = 16; off > 0; off >>= 1) xx += __shfl_down_sync(0xFFFFFFFFu, xx, off);
            if (lane == 0) sbase = xx;
        }
        __syncthreads();
        if (act) {
            int excl = sbase + wsum[wid] + incl - tsum;
            int4 rp = make_int4(excl, excl + q.x, excl + q.x + q.y, excl + q.x + q.y + q.z);
            *(int4*)(g_rowptr + base + 4 * t) = rp;
            *(int4*)(g_cur + base + 4 * t) = rp;
        }
        if (b == NSB - 1 && t == 0) g_rowptr[NNODES] = NEDGES;
    }
    // phase 2b: dis (all blocks, 64 nodes each; 313*64 >= 20000)
    if (t < 64) {
        int i = b * 64 + t;
        if (i < NNODES) {
            float dg = g_deg[i];
            g_dis[i] = dg > 0.f ? rsqrtf(fmaxf(dg, 1e-12f)) : 0.f;
        }
    }
    // grid barrier 2
    __syncthreads();
    if (t == 0) {
        __threadfence();
        atomicAdd((int*)&g_sync2, 1);
        while (g_sync2 < (int)gridDim.x) {}
    }
    __syncthreads();

    // phase 3: scatter (indices still in registers)
    if (ev) {
        float wa[4] = {wv.x, wv.y, wv.z, wv.w};
#pragma unroll
        for (int i = 0; i < 4; i++) {
            int pos = atomicAdd(&g_cur[d[i]], 1);
            g_ecol[pos] = s[i];
            g_enorm[pos] = g_dis[s[i]] * wa[i] * g_dis[d[i]];
        }
    }
}

// ---------------- fused gather SpMM for x and h (F=128), one warp per node ----------------
__global__ void k_gather_xh(const float* __restrict__ x, const float* __restrict__ h) {
    int warp = (blockIdx.x * blockDim.x + threadIdx.x) >> 5;
    int lane = threadIdx.x & 31;
    if (warp >= NNODES) return;
    int n = warp;
    float sd = g_dis[n];
    float s2 = sd * sd;
    float4 xv = *((const float4*)(x + (size_t)n * HD) + lane);
    float4 hv = *((const float4*)(h + (size_t)n * HD) + lane);
    float4 ax = make_float4(s2 * xv.x, s2 * xv.y, s2 * xv.z, s2 * xv.w);
    float4 ah = make_float4(s2 * hv.x, s2 * hv.y, s2 * hv.z, s2 * hv.w);
    int e0 = g_rowptr[n], e1 = g_rowptr[n + 1];
#pragma unroll 8
    for (int e = e0; e < e1; ++e) {
        int c = g_ecol[e];
        float nm = g_enorm[e];
        float4 cx = *((const float4*)(x + (size_t)c * HD) + lane);
        float4 ch = *((const float4*)(h + (size_t)c * HD) + lane);
        ax.x = fmaf(nm, cx.x, ax.x); ax.y = fmaf(nm, cx.y, ax.y);
        ax.z = fmaf(nm, cx.z, ax.z); ax.w = fmaf(nm, cx.w, ax.w);
        ah.x = fmaf(nm, ch.x, ah.x); ah.y = fmaf(nm, ch.y, ah.y);
        ah.z = fmaf(nm, ch.z, ah.z); ah.w = fmaf(nm, ch.w, ah.w);
    }
    ((float4*)(g_ax + (size_t)n * HD))[lane] = ax;
    ((float4*)(g_ah + (size_t)n * HD))[lane] = ah;
}

// ---------------- tensor-core GEMM building blocks (m16n8k16 bf16, 3-term split) ----------------
// 256 threads = 8 warps = 2m x 4n over a 64x128 tile; each warp: 32 rows (mt 2) x 32 cols (nt 4).
#define MMA_BF16(c, a, bb0, bb1) \
    asm("mma.sync.aligned.m16n8k16.row.col.f32.bf16.bf16.f32 " \
        "{%0,%1,%2,%3},{%4,%5,%6,%7},{%8,%9},{%0,%1,%2,%3};" \
        : "+f"(c[0]), "+f"(c[1]), "+f"(c[2]), "+f"(c[3]) \
        : "r"(a[0]), "r"(a[1]), "r"(a[2]), "r"(a[3]), "r"(bb0), "r"(bb1))

// volatile + memory clobber: the load must NOT be reordered across __syncthreads()
// or the shared-memory staging stores (buffers are re-staged / overwritten between passes).
#define LDSM_X4(r, addr) \
    asm volatile("ldmatrix.sync.aligned.m8n8.x4.shared.b16 {%0,%1,%2,%3}, [%4];" \
        : "=r"(r[0]), "=r"(r[1]), "=r"(r[2]), "=r"(r[3]) : "r"(addr) : "memory")

// stage a 64x128 fp32 tile from global, split into hi/lo bf16x2-pair smem arrays (256 thr)
__device__ __forceinline__ void stage_split(const float* __restrict__ A, int lda, int row0,
                                            unsigned* hi_arr, unsigned* lo_arr) {
    int tid = threadIdx.x;
    float4 v[8];
#pragma unroll
    for (int i = 0; i < 8; i++) {
        int f = i * 256 + tid;            // 0..2047
        int row = f >> 5;                 // 0..63
        int c4 = (f & 31) * 4;            // 0..124
        int grow = row0 + row;
        v[i] = (grow < NNODES) ? *(const float4*)(A + (size_t)grow * lda + c4)
                               : make_float4(0.f, 0.f, 0.f, 0.f);
    }
#pragma unroll
    for (int i = 0; i < 8; i++) {
        int f = i * 256 + tid;
        int row = f >> 5;
        int pc = (f & 31) * 2;            // pair column (even)
        unsigned h0, l0, h1, l1;
        bf16_split_pair(v[i].x, v[i].y, h0, l0);
        bf16_split_pair(v[i].z, v[i].w, h1, l1);
        hi_arr[row * FSTR + pc] = h0; hi_arr[row * FSTR + pc + 1] = h1;
        lo_arr[row * FSTR + pc] = l0; lo_arr[row * FSTR + pc + 1] = l1;
    }
}

// acc += (smem A tile) @ (pre-split B stream), 3-term split; A frags via ldmatrix
__device__ __forceinline__ void mma_pass(float (*acc)[4][4],
                                         const unsigned* As_hi, const unsigned* As_lo,
                                         int stream) {
    int tid = threadIdx.x;
    int wid = tid >> 5, lane = tid & 31;
    int wm = wid >> 2, wn = wid & 3;
    int m0 = wm * 32;
    const uint4* __restrict__ Bp = g_Bp + (stream << 12);
    int lrow = (lane & 7) + ((lane >> 3) & 1) * 8;
    int lcol = (lane >> 4) * 4;
    unsigned hi_base = (unsigned)__cvta_generic_to_shared(As_hi)
                     + ((m0 + lrow) * FSTR + lcol) * 4;
    unsigned lo_base = (unsigned)__cvta_generic_to_shared(As_lo)
                     + ((m0 + lrow) * FSTR + lcol) * 4;
#pragma unroll
    for (int ks = 0; ks < 8; ks++) {
        unsigned ahi[2][4], alo[2][4];
#pragma unroll
        for (int mt = 0; mt < 2; mt++) {
            unsigned off = (mt * 16 * FSTR + ks * 8) * 4;
            LDSM_X4(ahi[mt], hi_base + off);
            LDSM_X4(alo[mt], lo_base + off);
        }
#pragma unroll
        for (int nt = 0; nt < 4; nt++) {
            uint4 b = Bp[(ks * 16 + wn * 4 + nt) * 32 + lane];
#pragma unroll
            for (int mt = 0; mt < 2; mt++) {
                float* c = acc[mt][nt];
                MMA_BF16(c, ahi[mt], b.x, b.y);   // hi*hi
                MMA_BF16(c, ahi[mt], b.z, b.w);   // hi*lo
                MMA_BF16(c, alo[mt], b.x, b.y);   // lo*hi
            }
        }
    }
}

// relu(acc + bias) -> split -> z smem buffers (C-frag pair (c0,c1) is an adjacent k-pair)
__device__ __forceinline__ void store_z(float (*acc)[4][4], const float* __restrict__ bias,
                                        unsigned* zhi, unsigned* zlo) {
    int tid = threadIdx.x;
    int wid = tid >> 5, lane = tid & 31;
    int wm = wid >> 2, wn = wid & 3;
    int m0 = wm * 32, n0 = wn * 32;
    int tig = lane & 3, grp = lane >> 2;
#pragma unroll
    for (int nt = 0; nt < 4; nt++) {
        int col = n0 + nt * 8 + 2 * tig;
        float b0 = bias[col], b1 = bias[col + 1];
        int pc = col >> 1;
#pragma unroll
        for (int mt = 0; mt < 2; mt++) {
            int r = m0 + mt * 16 + grp;
            float* c = acc[mt][nt];
            float u0 = fmaxf(c[0] + b0, 0.f), u1 = fmaxf(c[1] + b1, 0.f);
            float u2 = fmaxf(c[2] + b0, 0.f), u3 = fmaxf(c[3] + b1, 0.f);
            unsigned h, l;
            bf16_split_pair(u0, u1, h, l);
            zhi[r * FSTR + pc] = h; zlo[r * FSTR + pc] = l;
            bf16_split_pair(u2, u3, h, l);
            zhi[(r + 8) * FSTR + pc] = h; zlo[(r + 8) * FSTR + pc] = l;
        }
    }
}

// write y as fp16 (halves gather traffic downstream)
__device__ __forceinline__ void gemm_epilogue_y16(float (*acc)[4][4],
                                                  __half* __restrict__ C, int ldc, int row0) {
    int tid = threadIdx.x;
    int wid = tid >> 5, lane = tid & 31;
    int wm = wid >> 2, wn = wid & 3;
    int m0 = wm * 32, n0 = wn * 32;
    int tig = lane & 3, grp = lane >> 2;
#pragma unroll
    for (int nt = 0; nt < 4; nt++) {
        int col = n0 + nt * 8 + 2 * tig;
#pragma unroll
        for (int mt = 0; mt < 2; mt++) {
            int r = row0 + m0 + mt * 16 + grp;
            float* c = acc[mt][nt];
            if (r < NNODES)
                *(__half2*)(C + (size_t)r * ldc + col) = __floats2half2_rn(c[0], c[1]);
            int r2 = r + 8;
            if (r2 < NNODES)
                *(__half2*)(C + (size_t)r2 * ldc + col) = __floats2half2_rn(c[2], c[3]);
        }
    }
}

// fused 2-layer GEMM per (gate, 64-row tile): z never leaves the SM. 256 threads, 2 blocks/SM.
__global__ __launch_bounds__(256) void k_mma_fused(const float* __restrict__ bx0,
                                                   const float* __restrict__ bh0) {
    extern __shared__ unsigned sm[];
    unsigned *Ah  = sm,            *Al  = sm + ZOFF;
    unsigned *zxh = sm + 2 * ZOFF, *zxl = sm + 3 * ZOFF;
    unsigned *zhh = sm + 4 * ZOFF, *zhl = sm + 5 * ZOFF;
    int g = blockIdx.y;
    int row0 = blockIdx.x * TM;

    // stage x -> (Ah,Al) and h -> (zhh,zhl) [h staging overlaps x MMA below]
    stage_split(g_ax, 128, row0, Ah, Al);
    stage_split(g_ah, 128, row0, zhh, zhl);
    __syncthreads();

    // layer-1 x-branch
    float accz[2][4][4];
#pragma unroll
    for (int a = 0; a < 2; a++)
#pragma unroll
        for (int b = 0; b < 4; b++)
#pragma unroll
            for (int cc = 0; cc < 4; cc++) accz[a][b][cc] = 0.f;
    mma_pass(accz, Ah, Al, g);
    store_z(accz, bx0 + g * 128, zxh, zxl);

    // layer-1 h-branch (A-h staged in zhh/zhl)
    float acch[2][4][4];
#pragma unroll
    for (int a = 0; a < 2; a++)
#pragma unroll
        for (int b = 0; b < 4; b++)
#pragma unroll
            for (int cc = 0; cc < 4; cc++) acch[a][b][cc] = 0.f;
    mma_pass(acch, zhh, zhl, 4 + g);
    __syncthreads();    // all warps finished reading A-h (and zxh writes now visible)
    store_z(acch, bh0 + g * 128, zhh, zhl);   // overwrite A-h with z_h
    __syncthreads();    // z_h visible

    // layer-2: y = z_x @ Wx1[g] + z_h @ Wh1[g]   (bias deferred to LSTM)
    float accy[2][4][4];
#pragma unroll
    for (int a = 0; a < 2; a++)
#pragma unroll
        for (int b = 0; b < 4; b++)
#pragma unroll
            for (int cc = 0; cc < 4; cc++) accy[a][b][cc] = 0.f;
    mma_pass(accy, zxh, zxl, 8 + g);
    mma_pass(accy, zhh, zhl, 12 + g);
    gemm_epilogue_y16(accy, g_y16 + g * 128, 512, row0);
}

// ---------------- fused F=512 gather (fp16 y) + LSTM epilogue: one block / node ----------------
__device__ __forceinline__ float sigmoidf_(float v) { return 1.f / (1.f + expf(-v)); }

__global__ void __launch_bounds__(128) k_gather_lstm(
    const float* __restrict__ c,
    const float* __restrict__ bx1, const float* __restrict__ bh1,
    const float* __restrict__ wc, const float* __restrict__ bg,
    float* __restrict__ out)
{
    __shared__ float sG[512];
    int n = blockIdx.x;
    int t = threadIdx.x;
    float sd = g_dis[n];
    float s2 = sd * sd;
    // thread t handles features 4t..4t+3 (8 bytes of fp16)
    uint2 raw = *(const uint2*)(g_y16 + (size_t)n * 512 + t * 4);
    float2 f0 = __half22float2(*(__half2*)&raw.x);
    float2 f1 = __half22float2(*(__half2*)&raw.y);
    float4 acc = make_float4(s2 * f0.x, s2 * f0.y, s2 * f1.x, s2 * f1.y);
    int e0 = g_rowptr[n], e1 = g_rowptr[n + 1];
#pragma unroll 8
    for (int e = e0; e < e1; ++e) {
        int cc = g_ecol[e];
        float nm = g_enorm[e];
        uint2 yr = *(const uint2*)(g_y16 + (size_t)cc * 512 + t * 4);
        float2 y0 = __half22float2(*(__half2*)&yr.x);
        float2 y1 = __half22float2(*(__half2*)&yr.y);
        acc.x = fmaf(nm, y0.x, acc.x); acc.y = fmaf(nm, y0.y, acc.y);
        acc.z = fmaf(nm, y1.x, acc.z); acc.w = fmaf(nm, y1.y, acc.w);
    }
    ((float4*)sG)[t] = acc;
    __syncthreads();
    int f = t;
    int idx = n * HD + f;
    float cv = c[idx];
    float Gi = sG[f]       + bx1[f]       + bh1[f];
    float Gf = sG[128 + f] + bx1[128 + f] + bh1[128 + f];
    float Gc = sG[256 + f] + bx1[256 + f] + bh1[256 + f];
    float Go = sG[384 + f] + bx1[384 + f] + bh1[384 + f];
    float I  = sigmoidf_(Gi + wc[f] * cv + bg[f]);
    float Fg = sigmoidf_(Gf + wc[128 + f] * cv + bg[128 + f]);
    float T  = tanhf(Gc + bg[256 + f]);
    float Cn = Fg * cv + I * T;
    float O  = sigmoidf_(Go + wc[256 + f] * Cn + bg[384 + f]);
    float Hn = O * tanhf(Cn);
    out[idx] = Hn;
    out[(size_t)NNODES * HD + idx] = Cn;
}

// ---------------- launch ----------------
extern "C" void kernel_launch(void* const* d_in, const int* in_sizes, int n_in,
                              void* d_out, int out_size) {
    const float* x   = (const float*)d_in[0];
    const void*  ei  = d_in[1];                 // int32 or int64, detected on device
    const float* w   = (const float*)d_in[2];
    const float* h   = (const float*)d_in[3];
    const float* c   = (const float*)d_in[4];
    const float* Wx0 = (const float*)d_in[5];
    const float* bx0 = (const float*)d_in[6];
    const float* Wx1 = (const float*)d_in[7];
    const float* bx1 = (const float*)d_in[8];
    const float* Wh0 = (const float*)d_in[9];
    const float* bh0 = (const float*)d_in[10];
    const float* Wh1 = (const float*)d_in[11];
    const float* bh1 = (const float*)d_in[12];
    const float* wc  = (const float*)d_in[13];
    const float* bg  = (const float*)d_in[14];
    float* out = (float*)d_out;

    static int smem_set = 0;
    if (!smem_set) {
        cudaFuncSetAttribute(k_mma_fused, cudaFuncAttributeMaxDynamicSharedMemorySize,
                             SMEM_FUSED_BYTES);
        smem_set = 1;
    }

    const int T = 256;
    // prologue: merged init+wprep, then single-kernel edge pipeline
    k_init_wprep<<<256 + (NNODES + T - 1) / T, T>>>((const int*)ei, Wx0, Wh0, Wx1, Wh1);
    k_edges<<<(NEDGES / 4 + T - 1) / T, T>>>(ei, w);

    // fused first props (F=128) for x and h, gather-based
    k_gather_xh<<<(NNODES * 32 + T - 1) / T, T>>>(x, h);

    // fused 2-layer tensor-core GEMM (z stays on-chip, y written fp16), 64-row tiles
    dim3 gm((NNODES + TM - 1) / TM, 4);
    k_mma_fused<<<gm, 256, SMEM_FUSED_BYTES>>>(bx0, bh0);

    // fused F=512 gather (fp16) + LSTM epilogue
    k_gather_lstm<<<NNODES, 128>>>(c, bx1, bh1, wc, bg, out);
}